// round 1
// baseline (speedup 1.0000x reference)
#include <cuda_runtime.h>
#include <math.h>

#define Bb 64
#define Kk 256
#define Tt 64
#define Dd 768
#define Nn 1024

// Scratch (static device globals -- no runtime allocation)
__device__ float g_v[(size_t)Bb * Kk * Nn];   // 67 MB  v[b,k,n]
__device__ float g_s[(size_t)Bb * Tt * Nn];   // 16 MB  scores -> alpha
__device__ float g_c[(size_t)Bb * Kk * Tt];   // 4 MB   c[b,k,t]
__device__ float g_lc[Bb * Tt];
__device__ float g_le[Bb * Tt];

// ---------------------------------------------------------------------------
// K1: v[b,k,n] = sum_d f[b,d,n] * W[d,k] + bias[k]
// Per batch: C(128k x 128n) tiles, BK=8, 256 threads, 8x8 microtile (quadrants)
// ---------------------------------------------------------------------------
__global__ __launch_bounds__(256) void k1_gemm_v(const float* __restrict__ f,
                                                 const float* __restrict__ W,
                                                 const float* __restrict__ bias) {
    __shared__ float Ws[8][128];
    __shared__ float Fs[8][128];
    const int b  = blockIdx.z;
    const int k0 = blockIdx.y * 128;
    const int n0 = blockIdx.x * 128;
    const int tid = threadIdx.x;
    const int tx = tid & 15, ty = tid >> 4;
    const int ld_d = tid >> 5;          // 0..7
    const int ld_c = (tid & 31) << 2;   // 0,4,...,124

    float acc[8][8];
#pragma unroll
    for (int i = 0; i < 8; i++)
#pragma unroll
        for (int j = 0; j < 8; j++) acc[i][j] = 0.0f;

    const float* fb = f + (size_t)b * Dd * Nn;

    for (int d0 = 0; d0 < Dd; d0 += 8) {
        *(float4*)&Ws[ld_d][ld_c] = *(const float4*)&W[(d0 + ld_d) * Kk + k0 + ld_c];
        *(float4*)&Fs[ld_d][ld_c] = *(const float4*)&fb[(size_t)(d0 + ld_d) * Nn + n0 + ld_c];
        __syncthreads();
#pragma unroll
        for (int d = 0; d < 8; d++) {
            float a[8], bv[8];
            *(float4*)&a[0]  = *(float4*)&Ws[d][ty * 4];
            *(float4*)&a[4]  = *(float4*)&Ws[d][64 + ty * 4];
            *(float4*)&bv[0] = *(float4*)&Fs[d][tx * 4];
            *(float4*)&bv[4] = *(float4*)&Fs[d][64 + tx * 4];
#pragma unroll
            for (int i = 0; i < 8; i++)
#pragma unroll
                for (int j = 0; j < 8; j++) acc[i][j] = fmaf(a[i], bv[j], acc[i][j]);
        }
        __syncthreads();
    }

    float* vb = g_v + (size_t)b * Kk * Nn;
#pragma unroll
    for (int i = 0; i < 8; i++) {
        const int k = k0 + ((i < 4) ? (ty * 4 + i) : (64 + ty * 4 + i - 4));
        const float bi = bias[k];
        float4 o0, o1;
        o0.x = acc[i][0] + bi; o0.y = acc[i][1] + bi; o0.z = acc[i][2] + bi; o0.w = acc[i][3] + bi;
        o1.x = acc[i][4] + bi; o1.y = acc[i][5] + bi; o1.z = acc[i][6] + bi; o1.w = acc[i][7] + bi;
        *(float4*)&vb[(size_t)k * Nn + n0 + tx * 4]      = o0;
        *(float4*)&vb[(size_t)k * Nn + n0 + 64 + tx * 4] = o1;
    }
}

// ---------------------------------------------------------------------------
// K2: s[b,t,n] = gamma * sum_k e[b,k,t] * v[b,k,n]
// Per batch: (64t x 128n) tiles, BK=8 over k, 256 threads, 4x8 microtile
// ---------------------------------------------------------------------------
__global__ __launch_bounds__(256) void k2_scores(const float* __restrict__ e,
                                                 const float* __restrict__ gamma) {
    __shared__ float Es[8][64];
    __shared__ float Vs[8][128];
    const int b  = blockIdx.y;
    const int n0 = blockIdx.x * 128;
    const int tid = threadIdx.x;
    const int tx = tid & 15, ty = tid >> 4;

    float acc[4][8];
#pragma unroll
    for (int i = 0; i < 4; i++)
#pragma unroll
        for (int j = 0; j < 8; j++) acc[i][j] = 0.0f;

    const float* eb = e + (size_t)b * Kk * Tt;
    const float* vb = g_v + (size_t)b * Kk * Nn;
    const int ld_k = tid >> 5;            // 0..7
    const int ld_t = (tid & 31) << 1;     // 0,2,...,62
    const int ld_n = (tid & 31) << 2;     // 0,4,...,124

    for (int k0 = 0; k0 < Kk; k0 += 8) {
        *(float2*)&Es[ld_k][ld_t] = *(const float2*)&eb[(k0 + ld_k) * Tt + ld_t];
        *(float4*)&Vs[ld_k][ld_n] = *(const float4*)&vb[(size_t)(k0 + ld_k) * Nn + n0 + ld_n];
        __syncthreads();
#pragma unroll
        for (int kk = 0; kk < 8; kk++) {
            float a[4], bv[8];
            *(float4*)&a[0]  = *(float4*)&Es[kk][ty * 4];
            *(float4*)&bv[0] = *(float4*)&Vs[kk][tx * 4];
            *(float4*)&bv[4] = *(float4*)&Vs[kk][64 + tx * 4];
#pragma unroll
            for (int i = 0; i < 4; i++)
#pragma unroll
                for (int j = 0; j < 8; j++) acc[i][j] = fmaf(a[i], bv[j], acc[i][j]);
        }
        __syncthreads();
    }

    const float g = *gamma;
    float* sb = g_s + (size_t)b * Tt * Nn;
#pragma unroll
    for (int i = 0; i < 4; i++) {
        const int t = ty * 4 + i;
        float4 o0, o1;
        o0.x = g * acc[i][0]; o0.y = g * acc[i][1]; o0.z = g * acc[i][2]; o0.w = g * acc[i][3];
        o1.x = g * acc[i][4]; o1.y = g * acc[i][5]; o1.z = g * acc[i][6]; o1.w = g * acc[i][7];
        *(float4*)&sb[(size_t)t * Nn + n0 + tx * 4]      = o0;
        *(float4*)&sb[(size_t)t * Nn + n0 + 64 + tx * 4] = o1;
    }
}

// ---------------------------------------------------------------------------
// K3: softmax over n (row length 1024), in-place on g_s
// ---------------------------------------------------------------------------
__global__ __launch_bounds__(256) void k3_softmax() {
    const int row = blockIdx.x;               // b*Tt + t
    float* s = g_s + (size_t)row * Nn;
    const int tid = threadIdx.x;
    const int w = tid >> 5, l = tid & 31;

    float4 x = *(float4*)&s[tid * 4];
    float m = fmaxf(fmaxf(x.x, x.y), fmaxf(x.z, x.w));
#pragma unroll
    for (int o = 16; o > 0; o >>= 1) m = fmaxf(m, __shfl_xor_sync(0xffffffffu, m, o));

    __shared__ float redm[8];
    __shared__ float reds[8];
    if (l == 0) redm[w] = m;
    __syncthreads();
    float mx = redm[0];
#pragma unroll
    for (int i = 1; i < 8; i++) mx = fmaxf(mx, redm[i]);

    float e0 = __expf(x.x - mx), e1 = __expf(x.y - mx);
    float e2 = __expf(x.z - mx), e3 = __expf(x.w - mx);
    float sum = e0 + e1 + e2 + e3;
#pragma unroll
    for (int o = 16; o > 0; o >>= 1) sum += __shfl_xor_sync(0xffffffffu, sum, o);
    if (l == 0) reds[w] = sum;
    __syncthreads();
    float tot = 0.0f;
#pragma unroll
    for (int i = 0; i < 8; i++) tot += reds[i];
    const float inv = 1.0f / tot;

    float4 o;
    o.x = e0 * inv; o.y = e1 * inv; o.z = e2 * inv; o.w = e3 * inv;
    *(float4*)&s[tid * 4] = o;
}

// ---------------------------------------------------------------------------
// K4: c[b,k,t] = sum_n v[b,k,n] * alpha[b,t,n]
// Per batch: (64k x 64t) tiles, BK=16 over n, transposed smem staging
// ---------------------------------------------------------------------------
__global__ __launch_bounds__(256) void k4_context() {
    __shared__ float Vs[16][65];
    __shared__ float As[16][65];
    const int b  = blockIdx.y;
    const int k0 = blockIdx.x * 64;
    const int tid = threadIdx.x;
    const int tx = tid & 15, ty = tid >> 4;

    float acc[4][4];
#pragma unroll
    for (int i = 0; i < 4; i++)
#pragma unroll
        for (int j = 0; j < 4; j++) acc[i][j] = 0.0f;

    const float* vb = g_v + (size_t)b * Kk * Nn;
    const float* ab = g_s + (size_t)b * Tt * Nn;
    const int lr = tid >> 2;            // 0..63 (k row / t row)
    const int ln = (tid & 3) << 2;      // 0,4,8,12

    for (int n0 = 0; n0 < Nn; n0 += 16) {
        float4 vv = *(const float4*)&vb[(size_t)(k0 + lr) * Nn + n0 + ln];
        Vs[ln + 0][lr] = vv.x; Vs[ln + 1][lr] = vv.y;
        Vs[ln + 2][lr] = vv.z; Vs[ln + 3][lr] = vv.w;
        float4 aa = *(const float4*)&ab[(size_t)lr * Nn + n0 + ln];
        As[ln + 0][lr] = aa.x; As[ln + 1][lr] = aa.y;
        As[ln + 2][lr] = aa.z; As[ln + 3][lr] = aa.w;
        __syncthreads();
#pragma unroll
        for (int nn = 0; nn < 16; nn++) {
            float a[4], bv[4];
#pragma unroll
            for (int i = 0; i < 4; i++) a[i]  = Vs[nn][ty * 4 + i];
#pragma unroll
            for (int j = 0; j < 4; j++) bv[j] = As[nn][tx * 4 + j];
#pragma unroll
            for (int i = 0; i < 4; i++)
#pragma unroll
                for (int j = 0; j < 4; j++) acc[i][j] = fmaf(a[i], bv[j], acc[i][j]);
        }
        __syncthreads();
    }

    float* cb = g_c + (size_t)b * Kk * Tt;
#pragma unroll
    for (int i = 0; i < 4; i++) {
        float4 o;
        o.x = acc[i][0]; o.y = acc[i][1]; o.z = acc[i][2]; o.w = acc[i][3];
        *(float4*)&cb[(size_t)(k0 + ty * 4 + i) * Tt + tx * 4] = o;
    }
}

// ---------------------------------------------------------------------------
// K5: per-token norms over feature axis k
// ---------------------------------------------------------------------------
__global__ void k5_norms(const float* __restrict__ e) {
    const int b = blockIdx.x;
    const int t = threadIdx.x;           // 0..63
    const float* eb = e   + (size_t)b * Kk * Tt;
    const float* cb = g_c + (size_t)b * Kk * Tt;
    float se = 0.0f, sc = 0.0f;
    for (int k = 0; k < Kk; k++) {
        float x = eb[k * Tt + t]; se = fmaf(x, x, se);
        float y = cb[k * Tt + t]; sc = fmaf(y, y, sc);
    }
    g_le[b * Tt + t] = sqrtf(se);
    g_lc[b * Tt + t] = sqrtf(sc);
}

// ---------------------------------------------------------------------------
// K6: cos[b,i,j] = (sum_k c[b,k,i]*e[b,k,j]) / (lc[i]*le[j])
// One block per batch, 64x64 output, BK=16 over k (both operands k-major)
// ---------------------------------------------------------------------------
__global__ __launch_bounds__(256) void k6_cos(const float* __restrict__ e,
                                              float* __restrict__ out) {
    __shared__ float Cs[16][64];
    __shared__ float Es[16][64];
    const int b = blockIdx.x;
    const int tid = threadIdx.x;
    const int tx = tid & 15, ty = tid >> 4;

    float acc[4][4];
#pragma unroll
    for (int i = 0; i < 4; i++)
#pragma unroll
        for (int j = 0; j < 4; j++) acc[i][j] = 0.0f;

    const float* cb = g_c + (size_t)b * Kk * Tt;
    const float* eb = e   + (size_t)b * Kk * Tt;
    const int lk = tid >> 4;            // 0..15
    const int lt = (tid & 15) << 2;     // 0,4,...,60

    for (int k0 = 0; k0 < Kk; k0 += 16) {
        *(float4*)&Cs[lk][lt] = *(const float4*)&cb[(k0 + lk) * Tt + lt];
        *(float4*)&Es[lk][lt] = *(const float4*)&eb[(k0 + lk) * Tt + lt];
        __syncthreads();
#pragma unroll
        for (int kk = 0; kk < 16; kk++) {
            float a[4], bv[4];
            *(float4*)&a[0]  = *(float4*)&Cs[kk][ty * 4];
            *(float4*)&bv[0] = *(float4*)&Es[kk][tx * 4];
#pragma unroll
            for (int i = 0; i < 4; i++)
#pragma unroll
                for (int j = 0; j < 4; j++) acc[i][j] = fmaf(a[i], bv[j], acc[i][j]);
        }
        __syncthreads();
    }

    float lci[4], lej[4];
#pragma unroll
    for (int i = 0; i < 4; i++) lci[i] = g_lc[b * Tt + ty * 4 + i];
#pragma unroll
    for (int j = 0; j < 4; j++) lej[j] = g_le[b * Tt + tx * 4 + j];

#pragma unroll
    for (int i = 0; i < 4; i++) {
        float4 o;
        o.x = acc[i][0] / (lci[i] * lej[0]);
        o.y = acc[i][1] / (lci[i] * lej[1]);
        o.z = acc[i][2] / (lci[i] * lej[2]);
        o.w = acc[i][3] / (lci[i] * lej[3]);
        *(float4*)&out[((size_t)b * Tt + ty * 4 + i) * Tt + tx * 4] = o;
    }
}

// ---------------------------------------------------------------------------
extern "C" void kernel_launch(void* const* d_in, const int* in_sizes, int n_in,
                              void* d_out, int out_size) {
    const float* e     = (const float*)d_in[0];
    const float* f     = (const float*)d_in[1];
    const float* gamma = (const float*)d_in[2];
    const float* W     = (const float*)d_in[3];
    const float* bias  = (const float*)d_in[4];
    float* out = (float*)d_out;

    k1_gemm_v<<<dim3(Nn / 128, Kk / 128, Bb), 256>>>(f, W, bias);
    k2_scores<<<dim3(Nn / 128, Bb), 256>>>(e, gamma);
    k3_softmax<<<Bb * Tt, 256>>>();
    k4_context<<<dim3(Kk / 64, Bb), 256>>>();
    k5_norms<<<Bb, Tt>>>(e);
    k6_cos<<<Bb, 256>>>(e, out);
}

// round 2
// speedup vs baseline: 1.2836x; 1.2836x over previous
#include <cuda_runtime.h>
#include <math.h>

#define Bb 64
#define Kk 256
#define Tt 64
#define Dd 768
#define Nn 1024

// Scratch (static device globals -- no runtime allocation)
__device__ float g_u[(size_t)Bb * Dd * Tt];   // 12.6 MB  u[b,d,t] = gamma * sum_k W[d,k] e[k,t]
__device__ float g_s[(size_t)Bb * Tt * Nn];   // 16 MB    scores -> alpha
__device__ float g_m[(size_t)Bb * Dd * Tt];   // 12.6 MB  m[b,d,t] = sum_n f[d,n] alpha[t,n]
__device__ float g_c[(size_t)Bb * Kk * Tt];   // 4 MB     c[b,k,t]
__device__ float g_lc[Bb * Tt];
__device__ float g_le[Bb * Tt];

// ---------------------------------------------------------------------------
// K_u: u[b,d,t] = gamma * sum_k W[d,k] * e[b,k,t]
// Per batch: 128d x 64t tiles, BK=8 over k, 256 threads, 8x4 microtile
// ---------------------------------------------------------------------------
__global__ __launch_bounds__(256) void k_u(const float* __restrict__ e,
                                           const float* __restrict__ W,
                                           const float* __restrict__ gamma) {
    __shared__ float Wt[128][12];   // [d][k] natural, padded (12%4==0 for float4 st)
    __shared__ float Es[8][64];     // [k][t]
    const int b  = blockIdx.y;
    const int d0 = blockIdx.x * 128;
    const int tid = threadIdx.x;
    const int tx = tid & 15, ty = tid >> 4;

    float acc[8][4];
#pragma unroll
    for (int i = 0; i < 8; i++)
#pragma unroll
        for (int j = 0; j < 4; j++) acc[i][j] = 0.0f;

    const float* eb = e + (size_t)b * Kk * Tt;
    const int wr = tid >> 1;            // 0..127  (d row)
    const int wc = (tid & 1) * 4;       // 0 or 4  (k col quad)
    const int ek = tid >> 5;            // 0..7
    const int et = (tid & 31) * 2;      // 0,2,...,62

    for (int k0 = 0; k0 < Kk; k0 += 8) {
        *(float4*)&Wt[wr][wc] = *(const float4*)&W[(size_t)(d0 + wr) * Kk + k0 + wc];
        *(float2*)&Es[ek][et] = *(const float2*)&eb[(k0 + ek) * Tt + et];
        __syncthreads();
#pragma unroll
        for (int kk = 0; kk < 8; kk++) {
            float a[8], bv[4];
#pragma unroll
            for (int i = 0; i < 8; i++) a[i] = Wt[ty * 8 + i][kk];
            *(float4*)&bv[0] = *(float4*)&Es[kk][tx * 4];
#pragma unroll
            for (int i = 0; i < 8; i++)
#pragma unroll
                for (int j = 0; j < 4; j++) acc[i][j] = fmaf(a[i], bv[j], acc[i][j]);
        }
        __syncthreads();
    }

    const float g = *gamma;
    float* ub = g_u + (size_t)b * Dd * Tt;
#pragma unroll
    for (int i = 0; i < 8; i++) {
        float4 o;
        o.x = g * acc[i][0]; o.y = g * acc[i][1];
        o.z = g * acc[i][2]; o.w = g * acc[i][3];
        *(float4*)&ub[(size_t)(d0 + ty * 8 + i) * Tt + tx * 4] = o;
    }
}

// ---------------------------------------------------------------------------
// K_s: s[b,t,n] = sum_d u[b,d,t] * f[b,d,n]   (gamma already folded into u)
// Per batch: 64t x 128n tiles, BK=8 over d, 256 threads, 4x8 microtile
// ---------------------------------------------------------------------------
__global__ __launch_bounds__(256) void k_s(const float* __restrict__ f) {
    __shared__ float Us[8][64];
    __shared__ float Fs[8][128];
    const int b  = blockIdx.y;
    const int n0 = blockIdx.x * 128;
    const int tid = threadIdx.x;
    const int tx = tid & 15, ty = tid >> 4;

    float acc[4][8];
#pragma unroll
    for (int i = 0; i < 4; i++)
#pragma unroll
        for (int j = 0; j < 8; j++) acc[i][j] = 0.0f;

    const float* ub = g_u + (size_t)b * Dd * Tt;
    const float* fb = f   + (size_t)b * Dd * Nn;
    const int ld_d = tid >> 5;            // 0..7
    const int ld_t = (tid & 31) * 2;
    const int ld_n = (tid & 31) * 4;

    for (int d0 = 0; d0 < Dd; d0 += 8) {
        *(float2*)&Us[ld_d][ld_t] = *(const float2*)&ub[(size_t)(d0 + ld_d) * Tt + ld_t];
        *(float4*)&Fs[ld_d][ld_n] = *(const float4*)&fb[(size_t)(d0 + ld_d) * Nn + n0 + ld_n];
        __syncthreads();
#pragma unroll
        for (int dd = 0; dd < 8; dd++) {
            float a[4], bv[8];
            *(float4*)&a[0]  = *(float4*)&Us[dd][ty * 4];
            *(float4*)&bv[0] = *(float4*)&Fs[dd][tx * 4];
            *(float4*)&bv[4] = *(float4*)&Fs[dd][64 + tx * 4];
#pragma unroll
            for (int i = 0; i < 4; i++)
#pragma unroll
                for (int j = 0; j < 8; j++) acc[i][j] = fmaf(a[i], bv[j], acc[i][j]);
        }
        __syncthreads();
    }

    float* sb = g_s + (size_t)b * Tt * Nn;
#pragma unroll
    for (int i = 0; i < 4; i++) {
        const int t = ty * 4 + i;
        float4 o0, o1;
        o0.x = acc[i][0]; o0.y = acc[i][1]; o0.z = acc[i][2]; o0.w = acc[i][3];
        o1.x = acc[i][4]; o1.y = acc[i][5]; o1.z = acc[i][6]; o1.w = acc[i][7];
        *(float4*)&sb[(size_t)t * Nn + n0 + tx * 4]      = o0;
        *(float4*)&sb[(size_t)t * Nn + n0 + 64 + tx * 4] = o1;
    }
}

// ---------------------------------------------------------------------------
// K3: softmax over n (row length 1024), in-place on g_s
// ---------------------------------------------------------------------------
__global__ __launch_bounds__(256) void k3_softmax() {
    const int row = blockIdx.x;               // b*Tt + t
    float* s = g_s + (size_t)row * Nn;
    const int tid = threadIdx.x;
    const int w = tid >> 5, l = tid & 31;

    float4 x = *(float4*)&s[tid * 4];
    float m = fmaxf(fmaxf(x.x, x.y), fmaxf(x.z, x.w));
#pragma unroll
    for (int o = 16; o > 0; o >>= 1) m = fmaxf(m, __shfl_xor_sync(0xffffffffu, m, o));

    __shared__ float redm[8];
    __shared__ float reds[8];
    if (l == 0) redm[w] = m;
    __syncthreads();
    float mx = redm[0];
#pragma unroll
    for (int i = 1; i < 8; i++) mx = fmaxf(mx, redm[i]);

    float e0 = __expf(x.x - mx), e1 = __expf(x.y - mx);
    float e2 = __expf(x.z - mx), e3 = __expf(x.w - mx);
    float sum = e0 + e1 + e2 + e3;
#pragma unroll
    for (int o = 16; o > 0; o >>= 1) sum += __shfl_xor_sync(0xffffffffu, sum, o);
    if (l == 0) reds[w] = sum;
    __syncthreads();
    float tot = 0.0f;
#pragma unroll
    for (int i = 0; i < 8; i++) tot += reds[i];
    const float inv = 1.0f / tot;

    float4 o;
    o.x = e0 * inv; o.y = e1 * inv; o.z = e2 * inv; o.w = e3 * inv;
    *(float4*)&s[tid * 4] = o;
}

// ---------------------------------------------------------------------------
// K_m: m[b,d,t] = sum_n f[b,d,n] * alpha[b,t,n]
// Per batch: 128d x 64t tiles, BN=16 over n, 256 threads, 8x4 microtile
// f staged natural [d][n], alpha staged transposed [n][t]
// ---------------------------------------------------------------------------
__global__ __launch_bounds__(256) void k_m(const float* __restrict__ f) {
    __shared__ float Fs[128][20];   // [d][n] natural, padded (20%4==0)
    __shared__ float As[16][68];    // [n][t] transposed
    const int b  = blockIdx.y;
    const int d0 = blockIdx.x * 128;
    const int tid = threadIdx.x;
    const int tx = tid & 15, ty = tid >> 4;

    float acc[8][4];
#pragma unroll
    for (int i = 0; i < 8; i++)
#pragma unroll
        for (int j = 0; j < 4; j++) acc[i][j] = 0.0f;

    const float* fb = f   + (size_t)b * Dd * Nn;
    const float* ab = g_s + (size_t)b * Tt * Nn;
    const int fr = tid >> 1;            // 0..127 (d row)
    const int fc = (tid & 1) * 8;       // 0 or 8 (n col base)
    const int ar = tid >> 2;            // 0..63  (t row)
    const int ac = (tid & 3) * 4;       // 0,4,8,12 (n col)

    for (int n0 = 0; n0 < Nn; n0 += 16) {
        *(float4*)&Fs[fr][fc]     = *(const float4*)&fb[(size_t)(d0 + fr) * Nn + n0 + fc];
        *(float4*)&Fs[fr][fc + 4] = *(const float4*)&fb[(size_t)(d0 + fr) * Nn + n0 + fc + 4];
        float4 aa = *(const float4*)&ab[(size_t)ar * Nn + n0 + ac];
        As[ac + 0][ar] = aa.x; As[ac + 1][ar] = aa.y;
        As[ac + 2][ar] = aa.z; As[ac + 3][ar] = aa.w;
        __syncthreads();
#pragma unroll
        for (int nn = 0; nn < 16; nn++) {
            float a[8], bv[4];
#pragma unroll
            for (int i = 0; i < 8; i++) a[i] = Fs[ty * 8 + i][nn];
            *(float4*)&bv[0] = *(float4*)&As[nn][tx * 4];
#pragma unroll
            for (int i = 0; i < 8; i++)
#pragma unroll
                for (int j = 0; j < 4; j++) acc[i][j] = fmaf(a[i], bv[j], acc[i][j]);
        }
        __syncthreads();
    }

    float* mb = g_m + (size_t)b * Dd * Tt;
#pragma unroll
    for (int i = 0; i < 8; i++) {
        float4 o;
        o.x = acc[i][0]; o.y = acc[i][1]; o.z = acc[i][2]; o.w = acc[i][3];
        *(float4*)&mb[(size_t)(d0 + ty * 8 + i) * Tt + tx * 4] = o;
    }
}

// ---------------------------------------------------------------------------
// K_c: c[b,k,t] = sum_d W[d,k] * m[b,d,t] + bias[k]
// Per batch: 64k x 64t tiles, BK=8 over d, 256 threads, 4x4 microtile
// ---------------------------------------------------------------------------
__global__ __launch_bounds__(256) void k_c(const float* __restrict__ W,
                                           const float* __restrict__ bias) {
    __shared__ float Wt[8][64];     // [d][k]
    __shared__ float Ms[8][64];     // [d][t]
    const int b  = blockIdx.y;
    const int k0 = blockIdx.x * 64;
    const int tid = threadIdx.x;
    const int tx = tid & 15, ty = tid >> 4;

    float acc[4][4];
#pragma unroll
    for (int i = 0; i < 4; i++)
#pragma unroll
        for (int j = 0; j < 4; j++) acc[i][j] = 0.0f;

    const float* mb = g_m + (size_t)b * Dd * Tt;
    const int dd = tid >> 5;            // 0..7
    const int cc = (tid & 31) * 2;      // 0,2,...,62

    for (int d0 = 0; d0 < Dd; d0 += 8) {
        *(float2*)&Wt[dd][cc] = *(const float2*)&W[(size_t)(d0 + dd) * Kk + k0 + cc];
        *(float2*)&Ms[dd][cc] = *(const float2*)&mb[(size_t)(d0 + dd) * Tt + cc];
        __syncthreads();
#pragma unroll
        for (int d = 0; d < 8; d++) {
            float a[4], bv[4];
            *(float4*)&a[0]  = *(float4*)&Wt[d][ty * 4];
            *(float4*)&bv[0] = *(float4*)&Ms[d][tx * 4];
#pragma unroll
            for (int i = 0; i < 4; i++)
#pragma unroll
                for (int j = 0; j < 4; j++) acc[i][j] = fmaf(a[i], bv[j], acc[i][j]);
        }
        __syncthreads();
    }

    float* cb = g_c + (size_t)b * Kk * Tt;
#pragma unroll
    for (int i = 0; i < 4; i++) {
        const int k = k0 + ty * 4 + i;
        const float bi = bias[k];
        float4 o;
        o.x = acc[i][0] + bi; o.y = acc[i][1] + bi;
        o.z = acc[i][2] + bi; o.w = acc[i][3] + bi;
        *(float4*)&cb[(size_t)k * Tt + tx * 4] = o;
    }
}

// ---------------------------------------------------------------------------
// K5: per-token norms over feature axis k
// ---------------------------------------------------------------------------
__global__ void k5_norms(const float* __restrict__ e) {
    const int b = blockIdx.x;
    const int t = threadIdx.x;           // 0..63
    const float* eb = e   + (size_t)b * Kk * Tt;
    const float* cb = g_c + (size_t)b * Kk * Tt;
    float se = 0.0f, sc = 0.0f;
    for (int k = 0; k < Kk; k++) {
        float x = eb[k * Tt + t]; se = fmaf(x, x, se);
        float y = cb[k * Tt + t]; sc = fmaf(y, y, sc);
    }
    g_le[b * Tt + t] = sqrtf(se);
    g_lc[b * Tt + t] = sqrtf(sc);
}

// ---------------------------------------------------------------------------
// K6: cos[b,i,j] = (sum_k c[b,k,i]*e[b,k,j]) / (lc[i]*le[j])
// ---------------------------------------------------------------------------
__global__ __launch_bounds__(256) void k6_cos(const float* __restrict__ e,
                                              float* __restrict__ out) {
    __shared__ float Cs[16][64];
    __shared__ float Es[16][64];
    const int b = blockIdx.x;
    const int tid = threadIdx.x;
    const int tx = tid & 15, ty = tid >> 4;

    float acc[4][4];
#pragma unroll
    for (int i = 0; i < 4; i++)
#pragma unroll
        for (int j = 0; j < 4; j++) acc[i][j] = 0.0f;

    const float* cb = g_c + (size_t)b * Kk * Tt;
    const float* eb = e   + (size_t)b * Kk * Tt;
    const int lk = tid >> 4;            // 0..15
    const int lt = (tid & 15) * 4;      // 0,4,...,60

    for (int k0 = 0; k0 < Kk; k0 += 16) {
        *(float4*)&Cs[lk][lt] = *(const float4*)&cb[(k0 + lk) * Tt + lt];
        *(float4*)&Es[lk][lt] = *(const float4*)&eb[(k0 + lk) * Tt + lt];
        __syncthreads();
#pragma unroll
        for (int kk = 0; kk < 16; kk++) {
            float a[4], bv[4];
            *(float4*)&a[0]  = *(float4*)&Cs[kk][ty * 4];
            *(float4*)&bv[0] = *(float4*)&Es[kk][tx * 4];
#pragma unroll
            for (int i = 0; i < 4; i++)
#pragma unroll
                for (int j = 0; j < 4; j++) acc[i][j] = fmaf(a[i], bv[j], acc[i][j]);
        }
        __syncthreads();
    }

    float lci[4], lej[4];
#pragma unroll
    for (int i = 0; i < 4; i++) lci[i] = g_lc[b * Tt + ty * 4 + i];
#pragma unroll
    for (int j = 0; j < 4; j++) lej[j] = g_le[b * Tt + tx * 4 + j];

#pragma unroll
    for (int i = 0; i < 4; i++) {
        float4 o;
        o.x = acc[i][0] / (lci[i] * lej[0]);
        o.y = acc[i][1] / (lci[i] * lej[1]);
        o.z = acc[i][2] / (lci[i] * lej[2]);
        o.w = acc[i][3] / (lci[i] * lej[3]);
        *(float4*)&out[((size_t)b * Tt + ty * 4 + i) * Tt + tx * 4] = o;
    }
}

// ---------------------------------------------------------------------------
extern "C" void kernel_launch(void* const* d_in, const int* in_sizes, int n_in,
                              void* d_out, int out_size) {
    const float* e     = (const float*)d_in[0];
    const float* f     = (const float*)d_in[1];
    const float* gamma = (const float*)d_in[2];
    const float* W     = (const float*)d_in[3];
    const float* bias  = (const float*)d_in[4];
    float* out = (float*)d_out;

    k_u<<<dim3(Dd / 128, Bb), 256>>>(e, W, gamma);
    k_s<<<dim3(Nn / 128, Bb), 256>>>(f);
    k3_softmax<<<Bb * Tt, 256>>>();
    k_m<<<dim3(Dd / 128, Bb), 256>>>(f);
    k_c<<<dim3(Kk / 64, Bb), 256>>>(W, bias);
    k5_norms<<<Bb, Tt>>>(e);
    k6_cos<<<Bb, 256>>>(e, out);
}

// round 4
// speedup vs baseline: 1.6359x; 1.2745x over previous
#include <cuda_runtime.h>
#include <cstdint>
#include <math.h>

#define Bb 64
#define Kk 256
#define Tt 64
#define Dd 768
#define Nn 1024

typedef unsigned long long ull;

// Scratch (static device globals -- no runtime allocation)
__device__ float g_u[(size_t)Bb * Dd * Tt];   // u[b][d][t] = gamma * Wt e
__device__ float g_s[(size_t)Bb * Tt * Nn];   // scores -> alpha
__device__ float g_m[(size_t)Bb * Dd * Tt];   // m[b][d][t]
__device__ float g_c[(size_t)Bb * Kk * Tt];   // c[b][k][t]
__device__ float g_lc[Bb * Tt];
__device__ float g_le[Bb * Tt];

// ---------------------------------------------------------------------------
// packed fp32x2 helpers
// ---------------------------------------------------------------------------
__device__ __forceinline__ ull dup2(float x) {
    ull r; asm("mov.b64 %0, {%1, %1};" : "=l"(r) : "f"(x)); return r;
}
__device__ __forceinline__ void ffma2(ull& d, ull a, ull b) {
    asm("fma.rn.f32x2 %0, %1, %2, %0;" : "+l"(d) : "l"(a), "l"(b));
}
__device__ __forceinline__ float2 unpk(ull v) {
    float2 r; asm("mov.b64 {%0, %1}, %2;" : "=f"(r.x), "=f"(r.y) : "l"(v)); return r;
}

// ---------------------------------------------------------------------------
// K_u: u[b,d,t] = gamma * sum_k W[d,k] * e[b,k,t]
// 128d x 64t tile, BK=16, 256 thr, micro 8d x 4t, d-pairs packed
// ---------------------------------------------------------------------------
__global__ __launch_bounds__(256) void k_u(const float* __restrict__ e,
                                           const float* __restrict__ W,
                                           const float* __restrict__ gamma) {
    __shared__ __align__(16) float Es[16][68];    // [k][t]
    __shared__ __align__(16) float Ws2[16][132];  // [k][d] transposed
    const int b  = blockIdx.y;
    const int d0 = blockIdx.x * 128;
    const int tid = threadIdx.x;
    const int tx = tid & 15, ty = tid >> 4;

    ull acc[4][4];
#pragma unroll
    for (int i = 0; i < 4; i++)
#pragma unroll
        for (int j = 0; j < 4; j++) acc[i][j] = 0ULL;

    const float* eb = e + (size_t)b * Kk * Tt;
    const int er = tid >> 4, eq = (tid & 15) * 4;
    const int wd = tid >> 1;

    for (int k0 = 0; k0 < Kk; k0 += 16) {
        *(float4*)&Es[er][eq] = *(const float4*)&eb[(k0 + er) * Tt + eq];
#pragma unroll
        for (int j = 0; j < 2; j++) {
            const int kq = (tid & 1) * 2 + j;
            float4 wv = *(const float4*)&W[(size_t)(d0 + wd) * Kk + k0 + kq * 4];
            Ws2[kq * 4 + 0][wd] = wv.x; Ws2[kq * 4 + 1][wd] = wv.y;
            Ws2[kq * 4 + 2][wd] = wv.z; Ws2[kq * 4 + 3][wd] = wv.w;
        }
        __syncthreads();
#pragma unroll
        for (int kk = 0; kk < 16; kk++) {
            ulonglong2 aL = *(ulonglong2*)&Ws2[kk][ty * 8];
            ulonglong2 aH = *(ulonglong2*)&Ws2[kk][ty * 8 + 4];
            ull ap[4] = {aL.x, aL.y, aH.x, aH.y};
            float4 b4 = *(float4*)&Es[kk][tx * 4];
            ull bd[4] = {dup2(b4.x), dup2(b4.y), dup2(b4.z), dup2(b4.w)};
#pragma unroll
            for (int i = 0; i < 4; i++)
#pragma unroll
                for (int j = 0; j < 4; j++) ffma2(acc[i][j], ap[i], bd[j]);
        }
        __syncthreads();
    }

    const float g = *gamma;
    float* ub = g_u + (size_t)b * Dd * Tt;
#pragma unroll
    for (int i = 0; i < 4; i++) {
        float2 p0 = unpk(acc[i][0]), p1 = unpk(acc[i][1]);
        float2 p2 = unpk(acc[i][2]), p3 = unpk(acc[i][3]);
        const int dlo = d0 + ty * 8 + 2 * i;
        float4 lo, hi;
        lo.x = g * p0.x; lo.y = g * p1.x; lo.z = g * p2.x; lo.w = g * p3.x;
        hi.x = g * p0.y; hi.y = g * p1.y; hi.z = g * p2.y; hi.w = g * p3.y;
        *(float4*)&ub[(size_t)dlo * Tt + tx * 4]       = lo;
        *(float4*)&ub[(size_t)(dlo + 1) * Tt + tx * 4] = hi;
    }
}

// ---------------------------------------------------------------------------
// K_s: s[b,t,n] = sum_d u[d,t] * f[d,n]  (gamma in u)
// 64t x 128n tile, BK=8 double-buffered, micro 4t x 8n, n-pairs packed
// ---------------------------------------------------------------------------
__global__ __launch_bounds__(256) void k_s(const float* __restrict__ f) {
    __shared__ __align__(16) float Us[2][8][68];
    __shared__ __align__(16) float Fs[2][8][132];
    const int b  = blockIdx.y;
    const int n0 = blockIdx.x * 128;
    const int tid = threadIdx.x;
    const int tx = tid & 15, ty = tid >> 4;

    ull acc[4][4];
#pragma unroll
    for (int i = 0; i < 4; i++)
#pragma unroll
        for (int j = 0; j < 4; j++) acc[i][j] = 0ULL;

    const float* ub = g_u + (size_t)b * Dd * Tt;
    const float* fb = f   + (size_t)b * Dd * Nn;
    const int ld_d = tid >> 5;
    const int ld_t = (tid & 31) * 2;
    const int ld_n = (tid & 31) * 4;

    float2 ur = *(const float2*)&ub[(size_t)ld_d * Tt + ld_t];
    float4 fr = *(const float4*)&fb[(size_t)ld_d * Nn + n0 + ld_n];

    int p = 0;
    for (int d0 = 0; d0 < Dd; d0 += 8) {
        *(float2*)&Us[p][ld_d][ld_t] = ur;
        *(float4*)&Fs[p][ld_d][ld_n] = fr;
        __syncthreads();
        if (d0 + 8 < Dd) {
            ur = *(const float2*)&ub[(size_t)(d0 + 8 + ld_d) * Tt + ld_t];
            fr = *(const float4*)&fb[(size_t)(d0 + 8 + ld_d) * Nn + n0 + ld_n];
        }
#pragma unroll
        for (int dd = 0; dd < 8; dd++) {
            float4 a4 = *(float4*)&Us[p][dd][ty * 4];
            ull ad[4] = {dup2(a4.x), dup2(a4.y), dup2(a4.z), dup2(a4.w)};
            ulonglong2 bL = *(ulonglong2*)&Fs[p][dd][tx * 4];
            ulonglong2 bH = *(ulonglong2*)&Fs[p][dd][64 + tx * 4];
            ull bp[4] = {bL.x, bL.y, bH.x, bH.y};
#pragma unroll
            for (int i = 0; i < 4; i++)
#pragma unroll
                for (int j = 0; j < 4; j++) ffma2(acc[i][j], ad[i], bp[j]);
        }
        p ^= 1;
    }

    float* sb = g_s + (size_t)b * Tt * Nn;
#pragma unroll
    for (int i = 0; i < 4; i++) {
        const int t = ty * 4 + i;
        float2 p0 = unpk(acc[i][0]), p1 = unpk(acc[i][1]);
        float2 p2 = unpk(acc[i][2]), p3 = unpk(acc[i][3]);
        float4 o0, o1;
        o0.x = p0.x; o0.y = p0.y; o0.z = p1.x; o0.w = p1.y;
        o1.x = p2.x; o1.y = p2.y; o1.z = p3.x; o1.w = p3.y;
        *(float4*)&sb[(size_t)t * Nn + n0 + tx * 4]      = o0;
        *(float4*)&sb[(size_t)t * Nn + n0 + 64 + tx * 4] = o1;
    }
}

// ---------------------------------------------------------------------------
// K3: softmax over n (1024), in-place
// ---------------------------------------------------------------------------
__global__ __launch_bounds__(256) void k3_softmax() {
    const int row = blockIdx.x;
    float* s = g_s + (size_t)row * Nn;
    const int tid = threadIdx.x;
    const int w = tid >> 5, l = tid & 31;

    float4 x = *(float4*)&s[tid * 4];
    float m = fmaxf(fmaxf(x.x, x.y), fmaxf(x.z, x.w));
#pragma unroll
    for (int o = 16; o > 0; o >>= 1) m = fmaxf(m, __shfl_xor_sync(0xffffffffu, m, o));

    __shared__ float redm[8];
    __shared__ float reds[8];
    if (l == 0) redm[w] = m;
    __syncthreads();
    float mx = redm[0];
#pragma unroll
    for (int i = 1; i < 8; i++) mx = fmaxf(mx, redm[i]);

    float e0 = __expf(x.x - mx), e1 = __expf(x.y - mx);
    float e2 = __expf(x.z - mx), e3 = __expf(x.w - mx);
    float sum = e0 + e1 + e2 + e3;
#pragma unroll
    for (int o = 16; o > 0; o >>= 1) sum += __shfl_xor_sync(0xffffffffu, sum, o);
    if (l == 0) reds[w] = sum;
    __syncthreads();
    float tot = 0.0f;
#pragma unroll
    for (int i = 0; i < 8; i++) tot += reds[i];
    const float inv = 1.0f / tot;

    float4 o;
    o.x = e0 * inv; o.y = e1 * inv; o.z = e2 * inv; o.w = e3 * inv;
    *(float4*)&s[tid * 4] = o;
}

// ---------------------------------------------------------------------------
// K_m: m[b,d,t] = sum_n f[d,n] * alpha[t,n]
// 128d x 64t tile, BN=16 double-buffered, micro 8d x 4t, d-pairs packed
// Ft staged transposed [n][d], As transposed [n][t]
// ---------------------------------------------------------------------------
__global__ __launch_bounds__(256) void k_m(const float* __restrict__ f) {
    __shared__ __align__(16) float Ft[2][16][136];
    __shared__ __align__(16) float As[2][16][72];
    const int b  = blockIdx.y;
    const int d0 = blockIdx.x * 128;
    const int tid = threadIdx.x;
    const int tx = tid & 15, ty = tid >> 4;

    ull acc[4][4];
#pragma unroll
    for (int i = 0; i < 4; i++)
#pragma unroll
        for (int j = 0; j < 4; j++) acc[i][j] = 0ULL;

    const float* fb = f   + (size_t)b * Dd * Nn;
    const float* ab = g_s + (size_t)b * Tt * Nn;
    const int fr = tid >> 1;            // 0..127 (d)
    const int fc = (tid & 1) * 8;       // n base 0/8
    const int ar = tid >> 2;            // 0..63 (t)
    const int ac = (tid & 3) * 4;       // n base

    float4 f0 = *(const float4*)&fb[(size_t)(d0 + fr) * Nn + fc];
    float4 f1 = *(const float4*)&fb[(size_t)(d0 + fr) * Nn + fc + 4];
    float4 a0 = *(const float4*)&ab[(size_t)ar * Nn + ac];

    int p = 0;
    for (int n0 = 0; n0 < Nn; n0 += 16) {
        Ft[p][fc + 0][fr] = f0.x; Ft[p][fc + 1][fr] = f0.y;
        Ft[p][fc + 2][fr] = f0.z; Ft[p][fc + 3][fr] = f0.w;
        Ft[p][fc + 4][fr] = f1.x; Ft[p][fc + 5][fr] = f1.y;
        Ft[p][fc + 6][fr] = f1.z; Ft[p][fc + 7][fr] = f1.w;
        As[p][ac + 0][ar] = a0.x; As[p][ac + 1][ar] = a0.y;
        As[p][ac + 2][ar] = a0.z; As[p][ac + 3][ar] = a0.w;
        __syncthreads();
        if (n0 + 16 < Nn) {
            f0 = *(const float4*)&fb[(size_t)(d0 + fr) * Nn + n0 + 16 + fc];
            f1 = *(const float4*)&fb[(size_t)(d0 + fr) * Nn + n0 + 16 + fc + 4];
            a0 = *(const float4*)&ab[(size_t)ar * Nn + n0 + 16 + ac];
        }
#pragma unroll
        for (int nn = 0; nn < 16; nn++) {
            ulonglong2 aL = *(ulonglong2*)&Ft[p][nn][ty * 8];
            ulonglong2 aH = *(ulonglong2*)&Ft[p][nn][ty * 8 + 4];
            ull ap[4] = {aL.x, aL.y, aH.x, aH.y};
            float4 b4 = *(float4*)&As[p][nn][tx * 4];
            ull bd[4] = {dup2(b4.x), dup2(b4.y), dup2(b4.z), dup2(b4.w)};
#pragma unroll
            for (int i = 0; i < 4; i++)
#pragma unroll
                for (int j = 0; j < 4; j++) ffma2(acc[i][j], ap[i], bd[j]);
        }
        p ^= 1;
    }

    float* mb = g_m + (size_t)b * Dd * Tt;
#pragma unroll
    for (int i = 0; i < 4; i++) {
        float2 p0 = unpk(acc[i][0]), p1 = unpk(acc[i][1]);
        float2 p2 = unpk(acc[i][2]), p3 = unpk(acc[i][3]);
        const int dlo = d0 + ty * 8 + 2 * i;
        float4 lo, hi;
        lo.x = p0.x; lo.y = p1.x; lo.z = p2.x; lo.w = p3.x;
        hi.x = p0.y; hi.y = p1.y; hi.z = p2.y; hi.w = p3.y;
        *(float4*)&mb[(size_t)dlo * Tt + tx * 4]       = lo;
        *(float4*)&mb[(size_t)(dlo + 1) * Tt + tx * 4] = hi;
    }
}

// ---------------------------------------------------------------------------
// K_c: c[b,k,t] = sum_d W[d,k] * m[b,d,t] + bias[k]
// 64k x 64t tile, BK=8, 256 thr, micro 4k x 4t, t-pairs packed
// ---------------------------------------------------------------------------
__global__ __launch_bounds__(256) void k_c(const float* __restrict__ W,
                                           const float* __restrict__ bias) {
    __shared__ __align__(16) float Wt[8][68];
    __shared__ __align__(16) float Ms[8][68];
    const int b  = blockIdx.y;
    const int k0 = blockIdx.x * 64;
    const int tid = threadIdx.x;
    const int tx = tid & 15, ty = tid >> 4;

    ull acc[4][2];
#pragma unroll
    for (int i = 0; i < 4; i++) { acc[i][0] = 0ULL; acc[i][1] = 0ULL; }

    const float* mb = g_m + (size_t)b * Dd * Tt;
    const int dd = tid >> 5;
    const int cc = (tid & 31) * 2;

    for (int d0 = 0; d0 < Dd; d0 += 8) {
        *(float2*)&Wt[dd][cc] = *(const float2*)&W[(size_t)(d0 + dd) * Kk + k0 + cc];
        *(float2*)&Ms[dd][cc] = *(const float2*)&mb[(size_t)(d0 + dd) * Tt + cc];
        __syncthreads();
#pragma unroll
        for (int d = 0; d < 8; d++) {
            float4 a4 = *(float4*)&Wt[d][ty * 4];
            ull ad[4] = {dup2(a4.x), dup2(a4.y), dup2(a4.z), dup2(a4.w)};
            ulonglong2 bp = *(ulonglong2*)&Ms[d][tx * 4];
#pragma unroll
            for (int i = 0; i < 4; i++) {
                ffma2(acc[i][0], ad[i], bp.x);
                ffma2(acc[i][1], ad[i], bp.y);
            }
        }
        __syncthreads();
    }

    float* cb = g_c + (size_t)b * Kk * Tt;
#pragma unroll
    for (int i = 0; i < 4; i++) {
        const int k = k0 + ty * 4 + i;
        const float bi = bias[k];
        float2 p0 = unpk(acc[i][0]), p1 = unpk(acc[i][1]);
        float4 o;
        o.x = p0.x + bi; o.y = p0.y + bi; o.z = p1.x + bi; o.w = p1.y + bi;
        *(float4*)&cb[(size_t)k * Tt + tx * 4] = o;
    }
}

// ---------------------------------------------------------------------------
// K5: per-token norms
// ---------------------------------------------------------------------------
__global__ void k5_norms(const float* __restrict__ e) {
    const int b = blockIdx.x;
    const int t = threadIdx.x;
    const float* eb = e   + (size_t)b * Kk * Tt;
    const float* cb = g_c + (size_t)b * Kk * Tt;
    float se = 0.0f, sc = 0.0f;
    for (int k = 0; k < Kk; k++) {
        float x = eb[k * Tt + t]; se = fmaf(x, x, se);
        float y = cb[k * Tt + t]; sc = fmaf(y, y, sc);
    }
    g_le[b * Tt + t] = sqrtf(se);
    g_lc[b * Tt + t] = sqrtf(sc);
}

// ---------------------------------------------------------------------------
// K6: cos[b,i,j] = (sum_k c[b,k,i]*e[b,k,j]) / (lc[i]*le[j])
// t-pairs packed on j
// ---------------------------------------------------------------------------
__global__ __launch_bounds__(256) void k6_cos(const float* __restrict__ e,
                                              float* __restrict__ out) {
    __shared__ __align__(16) float Cs[16][68];
    __shared__ __align__(16) float Es[16][68];
    const int b = blockIdx.x;
    const int tid = threadIdx.x;
    const int tx = tid & 15, ty = tid >> 4;

    ull acc[4][2];
#pragma unroll
    for (int i = 0; i < 4; i++) { acc[i][0] = 0ULL; acc[i][1] = 0ULL; }

    const float* cb = g_c + (size_t)b * Kk * Tt;
    const float* eb = e   + (size_t)b * Kk * Tt;
    const int lk = tid >> 4;
    const int lt = (tid & 15) * 4;

    for (int k0 = 0; k0 < Kk; k0 += 16) {
        *(float4*)&Cs[lk][lt] = *(const float4*)&cb[(k0 + lk) * Tt + lt];
        *(float4*)&Es[lk][lt] = *(const float4*)&eb[(k0 + lk) * Tt + lt];
        __syncthreads();
#pragma unroll
        for (int kk = 0; kk < 16; kk++) {
            float4 a4 = *(float4*)&Cs[kk][ty * 4];
            ull ad[4] = {dup2(a4.x), dup2(a4.y), dup2(a4.z), dup2(a4.w)};
            ulonglong2 bp = *(ulonglong2*)&Es[kk][tx * 4];
#pragma unroll
            for (int i = 0; i < 4; i++) {
                ffma2(acc[i][0], ad[i], bp.x);
                ffma2(acc[i][1], ad[i], bp.y);
            }
        }
        __syncthreads();
    }

    float lci[4];
#pragma unroll
    for (int i = 0; i < 4; i++) lci[i] = g_lc[b * Tt + ty * 4 + i];
    float lej[4];
#pragma unroll
    for (int j = 0; j < 4; j++) lej[j] = g_le[b * Tt + tx * 4 + j];

#pragma unroll
    for (int i = 0; i < 4; i++) {
        float2 p0 = unpk(acc[i][0]), p1 = unpk(acc[i][1]);
        float4 o;
        o.x = p0.x / (lci[i] * lej[0]);
        o.y = p0.y / (lci[i] * lej[1]);
        o.z = p1.x / (lci[i] * lej[2]);
        o.w = p1.y / (lci[i] * lej[3]);
        *(float4*)&out[((size_t)b * Tt + ty * 4 + i) * Tt + tx * 4] = o;
    }
}

// ---------------------------------------------------------------------------
extern "C" void kernel_launch(void* const* d_in, const int* in_sizes, int n_in,
                              void* d_out, int out_size) {
    const float* e     = (const float*)d_in[0];
    const float* f     = (const float*)d_in[1];
    const float* gamma = (const float*)d_in[2];
    const float* W     = (const float*)d_in[3];
    const float* bias  = (const float*)d_in[4];
    float* out = (float*)d_out;

    k_u<<<dim3(Dd / 128, Bb), 256>>>(e, W, gamma);
    k_s<<<dim3(Nn / 128, Bb), 256>>>(f);
    k3_softmax<<<Bb * Tt, 256>>>();
    k_m<<<dim3(Dd / 128, Bb), 256>>>(f);
    k_c<<<dim3(Kk / 64, Bb), 256>>>(W, bias);
    k5_norms<<<Bb, Tt>>>(e);
    k6_cos<<<Bb, 256>>>(e, out);
}

// round 5
// speedup vs baseline: 1.6726x; 1.0225x over previous
#include <cuda_runtime.h>
#include <cstdint>
#include <math.h>

#define Bb 64
#define Kk 256
#define Tt 64
#define Dd 768
#define Nn 1024

typedef unsigned long long ull;

// Scratch (static device globals -- no runtime allocation)
__device__ float g_u[(size_t)Bb * Dd * Tt];   // u[b][d][t] = gamma * Wt e
__device__ float g_s[(size_t)Bb * Tt * Nn];   // scores -> alpha
__device__ float g_m[(size_t)Bb * Dd * Tt];   // m[b][d][t]
__device__ float g_c[(size_t)Bb * Kk * Tt];   // c[b][k][t]
__device__ float g_lc[Bb * Tt];
__device__ float g_le[Bb * Tt];

// ---------------------------------------------------------------------------
// packed fp32x2 helpers
// ---------------------------------------------------------------------------
__device__ __forceinline__ ull dup2(float x) {
    ull r; asm("mov.b64 %0, {%1, %1};" : "=l"(r) : "f"(x)); return r;
}
__device__ __forceinline__ void ffma2(ull& d, ull a, ull b) {
    asm("fma.rn.f32x2 %0, %1, %2, %0;" : "+l"(d) : "l"(a), "l"(b));
}
__device__ __forceinline__ float2 unpk(ull v) {
    float2 r; asm("mov.b64 {%0, %1}, %2;" : "=f"(r.x), "=f"(r.y) : "l"(v)); return r;
}

// ---------------------------------------------------------------------------
// K_u: u[b,d,t] = gamma * sum_k W[d,k] * e[b,k,t]
// 128d x 64t tile, BK=16, 256 thr, micro 8d x 4t, d-pairs packed
// ---------------------------------------------------------------------------
__global__ __launch_bounds__(256) void k_u(const float* __restrict__ e,
                                           const float* __restrict__ W,
                                           const float* __restrict__ gamma) {
    __shared__ __align__(16) float Es[16][68];    // [k][t]
    __shared__ __align__(16) float Ws2[16][132];  // [k][d] transposed
    const int b  = blockIdx.y;
    const int d0 = blockIdx.x * 128;
    const int tid = threadIdx.x;
    const int tx = tid & 15, ty = tid >> 4;

    ull acc[4][4];
#pragma unroll
    for (int i = 0; i < 4; i++)
#pragma unroll
        for (int j = 0; j < 4; j++) acc[i][j] = 0ULL;

    const float* eb = e + (size_t)b * Kk * Tt;
    const int er = tid >> 4, eq = (tid & 15) * 4;
    const int wd = tid >> 1;

    for (int k0 = 0; k0 < Kk; k0 += 16) {
        *(float4*)&Es[er][eq] = *(const float4*)&eb[(k0 + er) * Tt + eq];
#pragma unroll
        for (int j = 0; j < 2; j++) {
            const int kq = (tid & 1) * 2 + j;
            float4 wv = *(const float4*)&W[(size_t)(d0 + wd) * Kk + k0 + kq * 4];
            Ws2[kq * 4 + 0][wd] = wv.x; Ws2[kq * 4 + 1][wd] = wv.y;
            Ws2[kq * 4 + 2][wd] = wv.z; Ws2[kq * 4 + 3][wd] = wv.w;
        }
        __syncthreads();
#pragma unroll
        for (int kk = 0; kk < 16; kk++) {
            ulonglong2 aL = *(ulonglong2*)&Ws2[kk][ty * 8];
            ulonglong2 aH = *(ulonglong2*)&Ws2[kk][ty * 8 + 4];
            ull ap[4] = {aL.x, aL.y, aH.x, aH.y};
            float4 b4 = *(float4*)&Es[kk][tx * 4];
            ull bd[4] = {dup2(b4.x), dup2(b4.y), dup2(b4.z), dup2(b4.w)};
#pragma unroll
            for (int i = 0; i < 4; i++)
#pragma unroll
                for (int j = 0; j < 4; j++) ffma2(acc[i][j], ap[i], bd[j]);
        }
        __syncthreads();
    }

    const float g = *gamma;
    float* ub = g_u + (size_t)b * Dd * Tt;
#pragma unroll
    for (int i = 0; i < 4; i++) {
        float2 p0 = unpk(acc[i][0]), p1 = unpk(acc[i][1]);
        float2 p2 = unpk(acc[i][2]), p3 = unpk(acc[i][3]);
        const int dlo = d0 + ty * 8 + 2 * i;
        float4 lo, hi;
        lo.x = g * p0.x; lo.y = g * p1.x; lo.z = g * p2.x; lo.w = g * p3.x;
        hi.x = g * p0.y; hi.y = g * p1.y; hi.z = g * p2.y; hi.w = g * p3.y;
        *(float4*)&ub[(size_t)dlo * Tt + tx * 4]       = lo;
        *(float4*)&ub[(size_t)(dlo + 1) * Tt + tx * 4] = hi;
    }
}

// ---------------------------------------------------------------------------
// K_s: s[b,t,n] = sum_d u[d,t] * f[d,n]  (gamma folded into u)
// 64t x 128n tile, 128 thr, BK=8 double-buffered, micro 8t(packed) x 8n(dup)
// n split as {tx*4..+3} and {64+tx*4..+3} for conflict-free LDS.128
// ---------------------------------------------------------------------------
__global__ __launch_bounds__(128) void k_s(const float* __restrict__ f) {
    __shared__ __align__(16) float Us[2][8][68];    // [d][t]
    __shared__ __align__(16) float Fs[2][8][132];   // [d][n]
    const int b  = blockIdx.y;
    const int n0 = blockIdx.x * 128;
    const int tid = threadIdx.x;
    const int tx = tid & 15;        // n-group
    const int ty = tid >> 4;        // 0..7, t-group of 8

    ull acc[4][8];                  // [t-pair][n]
#pragma unroll
    for (int i = 0; i < 4; i++)
#pragma unroll
        for (int j = 0; j < 8; j++) acc[i][j] = 0ULL;

    const float* ub = g_u + (size_t)b * Dd * Tt;
    const float* fb = f   + (size_t)b * Dd * Nn;
    const int ld_d = tid >> 4;            // 0..7
    const int ld_t = (tid & 15) * 4;
    const int ld_n = (tid & 15) * 8;

    float4 ur  = *(const float4*)&ub[(size_t)ld_d * Tt + ld_t];
    float4 fr0 = *(const float4*)&fb[(size_t)ld_d * Nn + n0 + ld_n];
    float4 fr1 = *(const float4*)&fb[(size_t)ld_d * Nn + n0 + ld_n + 4];

    int p = 0;
    for (int d0 = 0; d0 < Dd; d0 += 8) {
        *(float4*)&Us[p][ld_d][ld_t] = ur;
        *(float4*)&Fs[p][ld_d][ld_n]     = fr0;
        *(float4*)&Fs[p][ld_d][ld_n + 4] = fr1;
        __syncthreads();
        if (d0 + 8 < Dd) {
            ur  = *(const float4*)&ub[(size_t)(d0 + 8 + ld_d) * Tt + ld_t];
            fr0 = *(const float4*)&fb[(size_t)(d0 + 8 + ld_d) * Nn + n0 + ld_n];
            fr1 = *(const float4*)&fb[(size_t)(d0 + 8 + ld_d) * Nn + n0 + ld_n + 4];
        }
#pragma unroll
        for (int dd = 0; dd < 8; dd++) {
            ulonglong2 aL = *(ulonglong2*)&Us[p][dd][ty * 8];
            ulonglong2 aH = *(ulonglong2*)&Us[p][dd][ty * 8 + 4];
            ull ap[4] = {aL.x, aL.y, aH.x, aH.y};
            float4 b0 = *(float4*)&Fs[p][dd][tx * 4];
            float4 b1 = *(float4*)&Fs[p][dd][64 + tx * 4];
            ull bd[8] = {dup2(b0.x), dup2(b0.y), dup2(b0.z), dup2(b0.w),
                         dup2(b1.x), dup2(b1.y), dup2(b1.z), dup2(b1.w)};
#pragma unroll
            for (int i = 0; i < 4; i++)
#pragma unroll
                for (int j = 0; j < 8; j++) ffma2(acc[i][j], ap[i], bd[j]);
        }
        p ^= 1;
    }

    float* sb = g_s + (size_t)b * Tt * Nn;
#pragma unroll
    for (int i = 0; i < 4; i++) {
        const int t = ty * 8 + 2 * i;
        float2 q[8];
#pragma unroll
        for (int j = 0; j < 8; j++) q[j] = unpk(acc[i][j]);
        float4 lo0, lo1, hi0, hi1;
        lo0.x = q[0].x; lo0.y = q[1].x; lo0.z = q[2].x; lo0.w = q[3].x;
        lo1.x = q[4].x; lo1.y = q[5].x; lo1.z = q[6].x; lo1.w = q[7].x;
        hi0.x = q[0].y; hi0.y = q[1].y; hi0.z = q[2].y; hi0.w = q[3].y;
        hi1.x = q[4].y; hi1.y = q[5].y; hi1.z = q[6].y; hi1.w = q[7].y;
        *(float4*)&sb[(size_t)t * Nn + n0 + tx * 4]            = lo0;
        *(float4*)&sb[(size_t)t * Nn + n0 + 64 + tx * 4]       = lo1;
        *(float4*)&sb[(size_t)(t + 1) * Nn + n0 + tx * 4]      = hi0;
        *(float4*)&sb[(size_t)(t + 1) * Nn + n0 + 64 + tx * 4] = hi1;
    }
}

// ---------------------------------------------------------------------------
// K3: softmax over n (1024), in-place
// ---------------------------------------------------------------------------
__global__ __launch_bounds__(256) void k3_softmax() {
    const int row = blockIdx.x;
    float* s = g_s + (size_t)row * Nn;
    const int tid = threadIdx.x;
    const int w = tid >> 5, l = tid & 31;

    float4 x = *(float4*)&s[tid * 4];
    float m = fmaxf(fmaxf(x.x, x.y), fmaxf(x.z, x.w));
#pragma unroll
    for (int o = 16; o > 0; o >>= 1) m = fmaxf(m, __shfl_xor_sync(0xffffffffu, m, o));

    __shared__ float redm[8];
    __shared__ float reds[8];
    if (l == 0) redm[w] = m;
    __syncthreads();
    float mx = redm[0];
#pragma unroll
    for (int i = 1; i < 8; i++) mx = fmaxf(mx, redm[i]);

    float e0 = __expf(x.x - mx), e1 = __expf(x.y - mx);
    float e2 = __expf(x.z - mx), e3 = __expf(x.w - mx);
    float sum = e0 + e1 + e2 + e3;
#pragma unroll
    for (int o = 16; o > 0; o >>= 1) sum += __shfl_xor_sync(0xffffffffu, sum, o);
    if (l == 0) reds[w] = sum;
    __syncthreads();
    float tot = 0.0f;
#pragma unroll
    for (int i = 0; i < 8; i++) tot += reds[i];
    const float inv = 1.0f / tot;

    float4 o;
    o.x = e0 * inv; o.y = e1 * inv; o.z = e2 * inv; o.w = e3 * inv;
    *(float4*)&s[tid * 4] = o;
}

// ---------------------------------------------------------------------------
// K_m: m[b,d,t] = sum_n f[d,n] * alpha[t,n]
// 128d x 64t tile, 128 thr, BN=16 double-buffered, micro 8d(packed) x 8t(dup)
// t split as {tx*4..+3} and {32+tx*4..+3}
// Ft staged transposed [n][d], As transposed [n][t]
// ---------------------------------------------------------------------------
__global__ __launch_bounds__(128) void k_m(const float* __restrict__ f) {
    __shared__ __align__(16) float Ft[2][16][132];   // [n][d]
    __shared__ __align__(16) float As[2][16][68];    // [n][t]
    const int b  = blockIdx.y;
    const int d0 = blockIdx.x * 128;
    const int tid = threadIdx.x;
    const int tx  = tid & 7;        // t-group 0..7
    const int tyy = tid >> 3;       // d-group 0..15

    ull acc[4][8];                  // [d-pair][t]
#pragma unroll
    for (int i = 0; i < 4; i++)
#pragma unroll
        for (int j = 0; j < 8; j++) acc[i][j] = 0ULL;

    const float* fb = f   + (size_t)b * Dd * Nn;
    const float* ab = g_s + (size_t)b * Tt * Nn;
    const int fr = tid;             // d row 0..127
    const int ar = tid & 63;        // t row 0..63
    const int ac = (tid >> 6) * 8;  // n base 0/8

    float4 fv[4], av[2];
#pragma unroll
    for (int j = 0; j < 4; j++)
        fv[j] = *(const float4*)&fb[(size_t)(d0 + fr) * Nn + j * 4];
    av[0] = *(const float4*)&ab[(size_t)ar * Nn + ac];
    av[1] = *(const float4*)&ab[(size_t)ar * Nn + ac + 4];

    int p = 0;
    for (int n0 = 0; n0 < Nn; n0 += 16) {
#pragma unroll
        for (int j = 0; j < 4; j++) {
            Ft[p][j * 4 + 0][fr] = fv[j].x; Ft[p][j * 4 + 1][fr] = fv[j].y;
            Ft[p][j * 4 + 2][fr] = fv[j].z; Ft[p][j * 4 + 3][fr] = fv[j].w;
        }
#pragma unroll
        for (int j = 0; j < 2; j++) {
            As[p][ac + j * 4 + 0][ar] = av[j].x; As[p][ac + j * 4 + 1][ar] = av[j].y;
            As[p][ac + j * 4 + 2][ar] = av[j].z; As[p][ac + j * 4 + 3][ar] = av[j].w;
        }
        __syncthreads();
        if (n0 + 16 < Nn) {
#pragma unroll
            for (int j = 0; j < 4; j++)
                fv[j] = *(const float4*)&fb[(size_t)(d0 + fr) * Nn + n0 + 16 + j * 4];
            av[0] = *(const float4*)&ab[(size_t)ar * Nn + n0 + 16 + ac];
            av[1] = *(const float4*)&ab[(size_t)ar * Nn + n0 + 16 + ac + 4];
        }
#pragma unroll
        for (int nn = 0; nn < 16; nn++) {
            ulonglong2 aL = *(ulonglong2*)&Ft[p][nn][tyy * 8];
            ulonglong2 aH = *(ulonglong2*)&Ft[p][nn][tyy * 8 + 4];
            ull ap[4] = {aL.x, aL.y, aH.x, aH.y};
            float4 b0 = *(float4*)&As[p][nn][tx * 4];
            float4 b1 = *(float4*)&As[p][nn][32 + tx * 4];
            ull bd[8] = {dup2(b0.x), dup2(b0.y), dup2(b0.z), dup2(b0.w),
                         dup2(b1.x), dup2(b1.y), dup2(b1.z), dup2(b1.w)};
#pragma unroll
            for (int i = 0; i < 4; i++)
#pragma unroll
                for (int j = 0; j < 8; j++) ffma2(acc[i][j], ap[i], bd[j]);
        }
        p ^= 1;
    }

    float* mb = g_m + (size_t)b * Dd * Tt;
#pragma unroll
    for (int i = 0; i < 4; i++) {
        const int dlo = d0 + tyy * 8 + 2 * i;
        float2 q[8];
#pragma unroll
        for (int j = 0; j < 8; j++) q[j] = unpk(acc[i][j]);
        float4 lo0, lo1, hi0, hi1;
        lo0.x = q[0].x; lo0.y = q[1].x; lo0.z = q[2].x; lo0.w = q[3].x;
        lo1.x = q[4].x; lo1.y = q[5].x; lo1.z = q[6].x; lo1.w = q[7].x;
        hi0.x = q[0].y; hi0.y = q[1].y; hi0.z = q[2].y; hi0.w = q[3].y;
        hi1.x = q[4].y; hi1.y = q[5].y; hi1.z = q[6].y; hi1.w = q[7].y;
        *(float4*)&mb[(size_t)dlo * Tt + tx * 4]            = lo0;
        *(float4*)&mb[(size_t)dlo * Tt + 32 + tx * 4]       = lo1;
        *(float4*)&mb[(size_t)(dlo + 1) * Tt + tx * 4]      = hi0;
        *(float4*)&mb[(size_t)(dlo + 1) * Tt + 32 + tx * 4] = hi1;
    }
}

// ---------------------------------------------------------------------------
// K_c: c[b,k,t] = sum_d W[d,k] * m[b,d,t] + bias[k]
// 64k x 64t tile, BK=8, 256 thr, micro 4k x 4t, t-pairs packed
// ---------------------------------------------------------------------------
__global__ __launch_bounds__(256) void k_c(const float* __restrict__ W,
                                           const float* __restrict__ bias) {
    __shared__ __align__(16) float Wt[8][68];
    __shared__ __align__(16) float Ms[8][68];
    const int b  = blockIdx.y;
    const int k0 = blockIdx.x * 64;
    const int tid = threadIdx.x;
    const int tx = tid & 15, ty = tid >> 4;

    ull acc[4][2];
#pragma unroll
    for (int i = 0; i < 4; i++) { acc[i][0] = 0ULL; acc[i][1] = 0ULL; }

    const float* mb = g_m + (size_t)b * Dd * Tt;
    const int dd = tid >> 5;
    const int cc = (tid & 31) * 2;

    for (int d0 = 0; d0 < Dd; d0 += 8) {
        *(float2*)&Wt[dd][cc] = *(const float2*)&W[(size_t)(d0 + dd) * Kk + k0 + cc];
        *(float2*)&Ms[dd][cc] = *(const float2*)&mb[(size_t)(d0 + dd) * Tt + cc];
        __syncthreads();
#pragma unroll
        for (int d = 0; d < 8; d++) {
            float4 a4 = *(float4*)&Wt[d][ty * 4];
            ull ad[4] = {dup2(a4.x), dup2(a4.y), dup2(a4.z), dup2(a4.w)};
            ulonglong2 bp = *(ulonglong2*)&Ms[d][tx * 4];
#pragma unroll
            for (int i = 0; i < 4; i++) {
                ffma2(acc[i][0], ad[i], bp.x);
                ffma2(acc[i][1], ad[i], bp.y);
            }
        }
        __syncthreads();
    }

    float* cb = g_c + (size_t)b * Kk * Tt;
#pragma unroll
    for (int i = 0; i < 4; i++) {
        const int k = k0 + ty * 4 + i;
        const float bi = bias[k];
        float2 p0 = unpk(acc[i][0]), p1 = unpk(acc[i][1]);
        float4 o;
        o.x = p0.x + bi; o.y = p0.y + bi; o.z = p1.x + bi; o.w = p1.y + bi;
        *(float4*)&cb[(size_t)k * Tt + tx * 4] = o;
    }
}

// ---------------------------------------------------------------------------
// K5: per-token norms
// ---------------------------------------------------------------------------
__global__ void k5_norms(const float* __restrict__ e) {
    const int b = blockIdx.x;
    const int t = threadIdx.x;
    const float* eb = e   + (size_t)b * Kk * Tt;
    const float* cb = g_c + (size_t)b * Kk * Tt;
    float se = 0.0f, sc = 0.0f;
    for (int k = 0; k < Kk; k++) {
        float x = eb[k * Tt + t]; se = fmaf(x, x, se);
        float y = cb[k * Tt + t]; sc = fmaf(y, y, sc);
    }
    g_le[b * Tt + t] = sqrtf(se);
    g_lc[b * Tt + t] = sqrtf(sc);
}

// ---------------------------------------------------------------------------
// K6: cos[b,i,j] = (sum_k c[b,k,i]*e[b,k,j]) / (lc[i]*le[j])
// ---------------------------------------------------------------------------
__global__ __launch_bounds__(256) void k6_cos(const float* __restrict__ e,
                                              float* __restrict__ out) {
    __shared__ __align__(16) float Cs[16][68];
    __shared__ __align__(16) float Es[16][68];
    const int b = blockIdx.x;
    const int tid = threadIdx.x;
    const int tx = tid & 15, ty = tid >> 4;

    ull acc[4][2];
#pragma unroll
    for (int i = 0; i < 4; i++) { acc[i][0] = 0ULL; acc[i][1] = 0ULL; }

    const float* cb = g_c + (size_t)b * Kk * Tt;
    const float* eb = e   + (size_t)b * Kk * Tt;
    const int lk = tid >> 4;
    const int lt = (tid & 15) * 4;

    for (int k0 = 0; k0 < Kk; k0 += 16) {
        *(float4*)&Cs[lk][lt] = *(const float4*)&cb[(k0 + lk) * Tt + lt];
        *(float4*)&Es[lk][lt] = *(const float4*)&eb[(k0 + lk) * Tt + lt];
        __syncthreads();
#pragma unroll
        for (int kk = 0; kk < 16; kk++) {
            float4 a4 = *(float4*)&Cs[kk][ty * 4];
            ull ad[4] = {dup2(a4.x), dup2(a4.y), dup2(a4.z), dup2(a4.w)};
            ulonglong2 bp = *(ulonglong2*)&Es[kk][tx * 4];
#pragma unroll
            for (int i = 0; i < 4; i++) {
                ffma2(acc[i][0], ad[i], bp.x);
                ffma2(acc[i][1], ad[i], bp.y);
            }
        }
        __syncthreads();
    }

    float lci[4];
#pragma unroll
    for (int i = 0; i < 4; i++) lci[i] = g_lc[b * Tt + ty * 4 + i];
    float lej[4];
#pragma unroll
    for (int j = 0; j < 4; j++) lej[j] = g_le[b * Tt + tx * 4 + j];

#pragma unroll
    for (int i = 0; i < 4; i++) {
        float2 p0 = unpk(acc[i][0]), p1 = unpk(acc[i][1]);
        float4 o;
        o.x = p0.x / (lci[i] * lej[0]);
        o.y = p0.y / (lci[i] * lej[1]);
        o.z = p1.x / (lci[i] * lej[2]);
        o.w = p1.y / (lci[i] * lej[3]);
        *(float4*)&out[((size_t)b * Tt + ty * 4 + i) * Tt + tx * 4] = o;
    }
}

// ---------------------------------------------------------------------------
extern "C" void kernel_launch(void* const* d_in, const int* in_sizes, int n_in,
                              void* d_out, int out_size) {
    const float* e     = (const float*)d_in[0];
    const float* f     = (const float*)d_in[1];
    const float* gamma = (const float*)d_in[2];
    const float* W     = (const float*)d_in[3];
    const float* bias  = (const float*)d_in[4];
    float* out = (float*)d_out;

    k_u<<<dim3(Dd / 128, Bb), 256>>>(e, W, gamma);
    k_s<<<dim3(Nn / 128, Bb), 128>>>(f);
    k3_softmax<<<Bb * Tt, 256>>>();
    k_m<<<dim3(Dd / 128, Bb), 128>>>(f);
    k_c<<<dim3(Kk / 64, Bb), 256>>>(W, bias);
    k5_norms<<<Bb, Tt>>>(e);
    k6_cos<<<Bb, 256>>>(e, out);
}

// round 6
// speedup vs baseline: 1.7439x; 1.0426x over previous
#include <cuda_runtime.h>
#include <cstdint>
#include <math.h>

#define Bb 64
#define Kk 256
#define Tt 64
#define Dd 768
#define Nn 1024

typedef unsigned long long ull;

// Scratch (static device globals -- no runtime allocation)
__device__ float g_u[(size_t)Bb * Dd * Tt];        // u[b][d][t]
__device__ float g_sp[2][(size_t)Bb * Tt * Nn];    // partial scores (d-halves)
__device__ float g_s[(size_t)Bb * Tt * Nn];        // alpha
__device__ float g_mp[2][(size_t)Bb * Dd * Tt];    // partial m (n-halves)
__device__ float g_c[(size_t)Bb * Kk * Tt];        // c[b][k][t]
__device__ float g_lc[Bb * Tt];
__device__ float g_le[Bb * Tt];

// ---------------------------------------------------------------------------
// packed fp32x2 helpers
// ---------------------------------------------------------------------------
__device__ __forceinline__ ull dup2(float x) {
    ull r; asm("mov.b64 %0, {%1, %1};" : "=l"(r) : "f"(x)); return r;
}
__device__ __forceinline__ void ffma2(ull& d, ull a, ull b) {
    asm("fma.rn.f32x2 %0, %1, %2, %0;" : "+l"(d) : "l"(a), "l"(b));
}
__device__ __forceinline__ float2 unpk(ull v) {
    float2 r; asm("mov.b64 {%0, %1}, %2;" : "=f"(r.x), "=f"(r.y) : "l"(v)); return r;
}

// ---------------------------------------------------------------------------
// K_u: u[b,d,t] = gamma * sum_k W[d,k] * e[b,k,t]
// 128d x 64t tile, BK=16, 256 thr, micro 8d(packed) x 4t
// ---------------------------------------------------------------------------
__global__ __launch_bounds__(256) void k_u(const float* __restrict__ e,
                                           const float* __restrict__ W,
                                           const float* __restrict__ gamma) {
    __shared__ __align__(16) float Es[16][68];    // [k][t]
    __shared__ __align__(16) float Ws2[16][132];  // [k][d] transposed
    const int b  = blockIdx.y;
    const int d0 = blockIdx.x * 128;
    const int tid = threadIdx.x;
    const int tx = tid & 15, ty = tid >> 4;

    ull acc[4][4];
#pragma unroll
    for (int i = 0; i < 4; i++)
#pragma unroll
        for (int j = 0; j < 4; j++) acc[i][j] = 0ULL;

    const float* eb = e + (size_t)b * Kk * Tt;
    const int er = tid >> 4, eq = (tid & 15) * 4;
    const int wd = tid >> 1;

    for (int k0 = 0; k0 < Kk; k0 += 16) {
        *(float4*)&Es[er][eq] = *(const float4*)&eb[(k0 + er) * Tt + eq];
#pragma unroll
        for (int j = 0; j < 2; j++) {
            const int kq = (tid & 1) * 2 + j;
            float4 wv = *(const float4*)&W[(size_t)(d0 + wd) * Kk + k0 + kq * 4];
            Ws2[kq * 4 + 0][wd] = wv.x; Ws2[kq * 4 + 1][wd] = wv.y;
            Ws2[kq * 4 + 2][wd] = wv.z; Ws2[kq * 4 + 3][wd] = wv.w;
        }
        __syncthreads();
#pragma unroll
        for (int kk = 0; kk < 16; kk++) {
            ulonglong2 aL = *(ulonglong2*)&Ws2[kk][ty * 8];
            ulonglong2 aH = *(ulonglong2*)&Ws2[kk][ty * 8 + 4];
            ull ap[4] = {aL.x, aL.y, aH.x, aH.y};
            float4 b4 = *(float4*)&Es[kk][tx * 4];
            ull bd[4] = {dup2(b4.x), dup2(b4.y), dup2(b4.z), dup2(b4.w)};
#pragma unroll
            for (int i = 0; i < 4; i++)
#pragma unroll
                for (int j = 0; j < 4; j++) ffma2(acc[i][j], ap[i], bd[j]);
        }
        __syncthreads();
    }

    const float g = *gamma;
    float* ub = g_u + (size_t)b * Dd * Tt;
#pragma unroll
    for (int i = 0; i < 4; i++) {
        float2 p0 = unpk(acc[i][0]), p1 = unpk(acc[i][1]);
        float2 p2 = unpk(acc[i][2]), p3 = unpk(acc[i][3]);
        const int dlo = d0 + ty * 8 + 2 * i;
        float4 lo, hi;
        lo.x = g * p0.x; lo.y = g * p1.x; lo.z = g * p2.x; lo.w = g * p3.x;
        hi.x = g * p0.y; hi.y = g * p1.y; hi.z = g * p2.y; hi.w = g * p3.y;
        *(float4*)&ub[(size_t)dlo * Tt + tx * 4]       = lo;
        *(float4*)&ub[(size_t)(dlo + 1) * Tt + tx * 4] = hi;
    }
}

// ---------------------------------------------------------------------------
// K_s: s_part[dh][b,t,n] = sum_{d in half dh} u[d,t] * f[d,n]
// 64t x 128n tile, 128 thr, BK=8 double-buffered, micro 8t(packed) x 8n(dup)
// grid (8 nblk, 2 dhalf, 64 b)
// ---------------------------------------------------------------------------
__global__ __launch_bounds__(128) void k_s(const float* __restrict__ f) {
    __shared__ __align__(16) float Us[2][8][68];    // [d][t]
    __shared__ __align__(16) float Fs[2][8][132];   // [d][n]
    const int b  = blockIdx.z;
    const int dh = blockIdx.y;
    const int n0 = blockIdx.x * 128;
    const int tid = threadIdx.x;
    const int tx = tid & 15;
    const int ty = tid >> 4;

    ull acc[4][8];
#pragma unroll
    for (int i = 0; i < 4; i++)
#pragma unroll
        for (int j = 0; j < 8; j++) acc[i][j] = 0ULL;

    const float* ub = g_u + (size_t)b * Dd * Tt + (size_t)dh * (Dd / 2) * Tt;
    const float* fb = f   + (size_t)b * Dd * Nn + (size_t)dh * (Dd / 2) * Nn;
    const int ld_d = tid >> 4;
    const int ld_t = (tid & 15) * 4;
    const int ld_n = (tid & 15) * 8;

    float4 ur  = *(const float4*)&ub[(size_t)ld_d * Tt + ld_t];
    float4 fr0 = *(const float4*)&fb[(size_t)ld_d * Nn + n0 + ld_n];
    float4 fr1 = *(const float4*)&fb[(size_t)ld_d * Nn + n0 + ld_n + 4];

    int p = 0;
    for (int d0 = 0; d0 < Dd / 2; d0 += 8) {
        *(float4*)&Us[p][ld_d][ld_t] = ur;
        *(float4*)&Fs[p][ld_d][ld_n]     = fr0;
        *(float4*)&Fs[p][ld_d][ld_n + 4] = fr1;
        __syncthreads();
        if (d0 + 8 < Dd / 2) {
            ur  = *(const float4*)&ub[(size_t)(d0 + 8 + ld_d) * Tt + ld_t];
            fr0 = *(const float4*)&fb[(size_t)(d0 + 8 + ld_d) * Nn + n0 + ld_n];
            fr1 = *(const float4*)&fb[(size_t)(d0 + 8 + ld_d) * Nn + n0 + ld_n + 4];
        }
#pragma unroll
        for (int dd = 0; dd < 8; dd++) {
            ulonglong2 aL = *(ulonglong2*)&Us[p][dd][ty * 8];
            ulonglong2 aH = *(ulonglong2*)&Us[p][dd][ty * 8 + 4];
            ull ap[4] = {aL.x, aL.y, aH.x, aH.y};
            float4 b0 = *(float4*)&Fs[p][dd][tx * 4];
            float4 b1 = *(float4*)&Fs[p][dd][64 + tx * 4];
            ull bd[8] = {dup2(b0.x), dup2(b0.y), dup2(b0.z), dup2(b0.w),
                         dup2(b1.x), dup2(b1.y), dup2(b1.z), dup2(b1.w)};
#pragma unroll
            for (int i = 0; i < 4; i++)
#pragma unroll
                for (int j = 0; j < 8; j++) ffma2(acc[i][j], ap[i], bd[j]);
        }
        p ^= 1;
    }

    float* sb = g_sp[dh] + (size_t)b * Tt * Nn;
#pragma unroll
    for (int i = 0; i < 4; i++) {
        const int t = ty * 8 + 2 * i;
        float2 q[8];
#pragma unroll
        for (int j = 0; j < 8; j++) q[j] = unpk(acc[i][j]);
        float4 lo0, lo1, hi0, hi1;
        lo0.x = q[0].x; lo0.y = q[1].x; lo0.z = q[2].x; lo0.w = q[3].x;
        lo1.x = q[4].x; lo1.y = q[5].x; lo1.z = q[6].x; lo1.w = q[7].x;
        hi0.x = q[0].y; hi0.y = q[1].y; hi0.z = q[2].y; hi0.w = q[3].y;
        hi1.x = q[4].y; hi1.y = q[5].y; hi1.z = q[6].y; hi1.w = q[7].y;
        *(float4*)&sb[(size_t)t * Nn + n0 + tx * 4]            = lo0;
        *(float4*)&sb[(size_t)t * Nn + n0 + 64 + tx * 4]       = lo1;
        *(float4*)&sb[(size_t)(t + 1) * Nn + n0 + tx * 4]      = hi0;
        *(float4*)&sb[(size_t)(t + 1) * Nn + n0 + 64 + tx * 4] = hi1;
    }
}

// ---------------------------------------------------------------------------
// K3: alpha = softmax(s0 + s1) over n (1024)
// ---------------------------------------------------------------------------
__global__ __launch_bounds__(256) void k3_softmax() {
    const int row = blockIdx.x;
    const float* s0 = g_sp[0] + (size_t)row * Nn;
    const float* s1 = g_sp[1] + (size_t)row * Nn;
    float* sa = g_s + (size_t)row * Nn;
    const int tid = threadIdx.x;
    const int w = tid >> 5, l = tid & 31;

    float4 x0 = *(const float4*)&s0[tid * 4];
    float4 x1 = *(const float4*)&s1[tid * 4];
    float4 x;
    x.x = x0.x + x1.x; x.y = x0.y + x1.y; x.z = x0.z + x1.z; x.w = x0.w + x1.w;

    float m = fmaxf(fmaxf(x.x, x.y), fmaxf(x.z, x.w));
#pragma unroll
    for (int o = 16; o > 0; o >>= 1) m = fmaxf(m, __shfl_xor_sync(0xffffffffu, m, o));

    __shared__ float redm[8];
    __shared__ float reds[8];
    if (l == 0) redm[w] = m;
    __syncthreads();
    float mx = redm[0];
#pragma unroll
    for (int i = 1; i < 8; i++) mx = fmaxf(mx, redm[i]);

    float e0 = __expf(x.x - mx), e1 = __expf(x.y - mx);
    float e2 = __expf(x.z - mx), e3 = __expf(x.w - mx);
    float sum = e0 + e1 + e2 + e3;
#pragma unroll
    for (int o = 16; o > 0; o >>= 1) sum += __shfl_xor_sync(0xffffffffu, sum, o);
    if (l == 0) reds[w] = sum;
    __syncthreads();
    float tot = 0.0f;
#pragma unroll
    for (int i = 0; i < 8; i++) tot += reds[i];
    const float inv = 1.0f / tot;

    float4 o;
    o.x = e0 * inv; o.y = e1 * inv; o.z = e2 * inv; o.w = e3 * inv;
    *(float4*)&sa[tid * 4] = o;
}

// ---------------------------------------------------------------------------
// K_m: m_part[nh][b,d,t] = sum_{n in half nh} f[d,n] * alpha[t,n]
// 128d x 64t tile, 128 thr, BN=16 double-buffered, micro 8d(packed) x 8t(dup)
// grid (6 dblk, 2 nhalf, 64 b)
// ---------------------------------------------------------------------------
__global__ __launch_bounds__(128) void k_m(const float* __restrict__ f) {
    __shared__ __align__(16) float Ft[2][16][132];   // [n][d]
    __shared__ __align__(16) float As[2][16][68];    // [n][t]
    const int b  = blockIdx.z;
    const int nh = blockIdx.y;
    const int d0 = blockIdx.x * 128;
    const int tid = threadIdx.x;
    const int tx  = tid & 7;
    const int tyy = tid >> 3;

    ull acc[4][8];
#pragma unroll
    for (int i = 0; i < 4; i++)
#pragma unroll
        for (int j = 0; j < 8; j++) acc[i][j] = 0ULL;

    const float* fb = f   + (size_t)b * Dd * Nn + (size_t)nh * (Nn / 2);
    const float* ab = g_s + (size_t)b * Tt * Nn + (size_t)nh * (Nn / 2);
    const int fr = tid;
    const int ar = tid & 63;
    const int ac = (tid >> 6) * 8;

    float4 fv[4], av[2];
#pragma unroll
    for (int j = 0; j < 4; j++)
        fv[j] = *(const float4*)&fb[(size_t)(d0 + fr) * Nn + j * 4];
    av[0] = *(const float4*)&ab[(size_t)ar * Nn + ac];
    av[1] = *(const float4*)&ab[(size_t)ar * Nn + ac + 4];

    int p = 0;
    for (int n0 = 0; n0 < Nn / 2; n0 += 16) {
#pragma unroll
        for (int j = 0; j < 4; j++) {
            Ft[p][j * 4 + 0][fr] = fv[j].x; Ft[p][j * 4 + 1][fr] = fv[j].y;
            Ft[p][j * 4 + 2][fr] = fv[j].z; Ft[p][j * 4 + 3][fr] = fv[j].w;
        }
#pragma unroll
        for (int j = 0; j < 2; j++) {
            As[p][ac + j * 4 + 0][ar] = av[j].x; As[p][ac + j * 4 + 1][ar] = av[j].y;
            As[p][ac + j * 4 + 2][ar] = av[j].z; As[p][ac + j * 4 + 3][ar] = av[j].w;
        }
        __syncthreads();
        if (n0 + 16 < Nn / 2) {
#pragma unroll
            for (int j = 0; j < 4; j++)
                fv[j] = *(const float4*)&fb[(size_t)(d0 + fr) * Nn + n0 + 16 + j * 4];
            av[0] = *(const float4*)&ab[(size_t)ar * Nn + n0 + 16 + ac];
            av[1] = *(const float4*)&ab[(size_t)ar * Nn + n0 + 16 + ac + 4];
        }
#pragma unroll
        for (int nn = 0; nn < 16; nn++) {
            ulonglong2 aL = *(ulonglong2*)&Ft[p][nn][tyy * 8];
            ulonglong2 aH = *(ulonglong2*)&Ft[p][nn][tyy * 8 + 4];
            ull ap[4] = {aL.x, aL.y, aH.x, aH.y};
            float4 b0 = *(float4*)&As[p][nn][tx * 4];
            float4 b1 = *(float4*)&As[p][nn][32 + tx * 4];
            ull bd[8] = {dup2(b0.x), dup2(b0.y), dup2(b0.z), dup2(b0.w),
                         dup2(b1.x), dup2(b1.y), dup2(b1.z), dup2(b1.w)};
#pragma unroll
            for (int i = 0; i < 4; i++)
#pragma unroll
                for (int j = 0; j < 8; j++) ffma2(acc[i][j], ap[i], bd[j]);
        }
        p ^= 1;
    }

    float* mb = g_mp[nh] + (size_t)b * Dd * Tt;
#pragma unroll
    for (int i = 0; i < 4; i++) {
        const int dlo = d0 + tyy * 8 + 2 * i;
        float2 q[8];
#pragma unroll
        for (int j = 0; j < 8; j++) q[j] = unpk(acc[i][j]);
        float4 lo0, lo1, hi0, hi1;
        lo0.x = q[0].x; lo0.y = q[1].x; lo0.z = q[2].x; lo0.w = q[3].x;
        lo1.x = q[4].x; lo1.y = q[5].x; lo1.z = q[6].x; lo1.w = q[7].x;
        hi0.x = q[0].y; hi0.y = q[1].y; hi0.z = q[2].y; hi0.w = q[3].y;
        hi1.x = q[4].y; hi1.y = q[5].y; hi1.z = q[6].y; hi1.w = q[7].y;
        *(float4*)&mb[(size_t)dlo * Tt + tx * 4]            = lo0;
        *(float4*)&mb[(size_t)dlo * Tt + 32 + tx * 4]       = lo1;
        *(float4*)&mb[(size_t)(dlo + 1) * Tt + tx * 4]      = hi0;
        *(float4*)&mb[(size_t)(dlo + 1) * Tt + 32 + tx * 4] = hi1;
    }
}

// ---------------------------------------------------------------------------
// K_c: c[b,k,t] = sum_d W[d,k] * (m0+m1)[b,d,t] + bias[k]
// ---------------------------------------------------------------------------
__global__ __launch_bounds__(256) void k_c(const float* __restrict__ W,
                                           const float* __restrict__ bias) {
    __shared__ __align__(16) float Wt[8][68];
    __shared__ __align__(16) float Ms[8][68];
    const int b  = blockIdx.y;
    const int k0 = blockIdx.x * 64;
    const int tid = threadIdx.x;
    const int tx = tid & 15, ty = tid >> 4;

    ull acc[4][2];
#pragma unroll
    for (int i = 0; i < 4; i++) { acc[i][0] = 0ULL; acc[i][1] = 0ULL; }

    const float* mb0 = g_mp[0] + (size_t)b * Dd * Tt;
    const float* mb1 = g_mp[1] + (size_t)b * Dd * Tt;
    const int dd = tid >> 5;
    const int cc = (tid & 31) * 2;

    for (int d0 = 0; d0 < Dd; d0 += 8) {
        *(float2*)&Wt[dd][cc] = *(const float2*)&W[(size_t)(d0 + dd) * Kk + k0 + cc];
        float2 ma = *(const float2*)&mb0[(size_t)(d0 + dd) * Tt + cc];
        float2 mc = *(const float2*)&mb1[(size_t)(d0 + dd) * Tt + cc];
        Ms[dd][cc] = ma.x + mc.x; Ms[dd][cc + 1] = ma.y + mc.y;
        __syncthreads();
#pragma unroll
        for (int d = 0; d < 8; d++) {
            float4 a4 = *(float4*)&Wt[d][ty * 4];
            ull ad[4] = {dup2(a4.x), dup2(a4.y), dup2(a4.z), dup2(a4.w)};
            ulonglong2 bp = *(ulonglong2*)&Ms[d][tx * 4];
#pragma unroll
            for (int i = 0; i < 4; i++) {
                ffma2(acc[i][0], ad[i], bp.x);
                ffma2(acc[i][1], ad[i], bp.y);
            }
        }
        __syncthreads();
    }

    float* cb = g_c + (size_t)b * Kk * Tt;
#pragma unroll
    for (int i = 0; i < 4; i++) {
        const int k = k0 + ty * 4 + i;
        const float bi = bias[k];
        float2 p0 = unpk(acc[i][0]), p1 = unpk(acc[i][1]);
        float4 o;
        o.x = p0.x + bi; o.y = p0.y + bi; o.z = p1.x + bi; o.w = p1.y + bi;
        *(float4*)&cb[(size_t)k * Tt + tx * 4] = o;
    }
}

// ---------------------------------------------------------------------------
// K5: per-token norms, 256 thr, k split x4 with smem reduce
// ---------------------------------------------------------------------------
__global__ __launch_bounds__(256) void k5_norms(const float* __restrict__ e) {
    __shared__ float re[4][64];
    __shared__ float rc[4][64];
    const int b = blockIdx.x;
    const int tid = threadIdx.x;
    const int t = tid & 63, q = tid >> 6;
    const float* eb = e   + (size_t)b * Kk * Tt;
    const float* cb = g_c + (size_t)b * Kk * Tt;
    float se = 0.0f, sc = 0.0f;
    for (int k = q * 64; k < q * 64 + 64; k++) {
        float x = eb[k * Tt + t]; se = fmaf(x, x, se);
        float y = cb[k * Tt + t]; sc = fmaf(y, y, sc);
    }
    re[q][t] = se; rc[q][t] = sc;
    __syncthreads();
    if (tid < 64) {
        float a = re[0][tid] + re[1][tid] + re[2][tid] + re[3][tid];
        float d = rc[0][tid] + rc[1][tid] + rc[2][tid] + rc[3][tid];
        g_le[b * Tt + tid] = sqrtf(a);
        g_lc[b * Tt + tid] = sqrtf(d);
    }
}

// ---------------------------------------------------------------------------
// K6: cos[b,i,j] = (sum_k c[b,k,i]*e[b,k,j]) / (lc[i]*le[j])
// grid (2 ihalf, 64 b), 256 thr, micro 2i x 4j (j pairs packed)
// ---------------------------------------------------------------------------
__global__ __launch_bounds__(256) void k6_cos(const float* __restrict__ e,
                                              float* __restrict__ out) {
    __shared__ __align__(16) float Cs[16][36];
    __shared__ __align__(16) float Es[16][68];
    const int ih = blockIdx.x;
    const int b  = blockIdx.y;
    const int tid = threadIdx.x;
    const int tx = tid & 15, ty = tid >> 4;

    ull acc[2][2];
    acc[0][0] = acc[0][1] = acc[1][0] = acc[1][1] = 0ULL;

    const float* cb = g_c + (size_t)b * Kk * Tt;
    const float* eb = e   + (size_t)b * Kk * Tt;
    const int lk = tid >> 4;
    const int ltE = (tid & 15) * 4;
    const int ltC = (tid & 15) * 2;

    for (int k0 = 0; k0 < Kk; k0 += 16) {
        *(float2*)&Cs[lk][ltC] = *(const float2*)&cb[(k0 + lk) * Tt + ih * 32 + ltC];
        *(float4*)&Es[lk][ltE] = *(const float4*)&eb[(k0 + lk) * Tt + ltE];
        __syncthreads();
#pragma unroll
        for (int kk = 0; kk < 16; kk++) {
            float2 a2 = *(float2*)&Cs[kk][ty * 2];
            ull ad[2] = {dup2(a2.x), dup2(a2.y)};
            ulonglong2 bp = *(ulonglong2*)&Es[kk][tx * 4];
#pragma unroll
            for (int i = 0; i < 2; i++) {
                ffma2(acc[i][0], ad[i], bp.x);
                ffma2(acc[i][1], ad[i], bp.y);
            }
        }
        __syncthreads();
    }

    float lci[2], lej[4];
#pragma unroll
    for (int i = 0; i < 2; i++) lci[i] = g_lc[b * Tt + ih * 32 + ty * 2 + i];
#pragma unroll
    for (int j = 0; j < 4; j++) lej[j] = g_le[b * Tt + tx * 4 + j];

#pragma unroll
    for (int i = 0; i < 2; i++) {
        const int irow = ih * 32 + ty * 2 + i;
        float2 p0 = unpk(acc[i][0]), p1 = unpk(acc[i][1]);
        float4 o;
        o.x = p0.x / (lci[i] * lej[0]);
        o.y = p0.y / (lci[i] * lej[1]);
        o.z = p1.x / (lci[i] * lej[2]);
        o.w = p1.y / (lci[i] * lej[3]);
        *(float4*)&out[((size_t)b * Tt + irow) * Tt + tx * 4] = o;
    }
}

// ---------------------------------------------------------------------------
extern "C" void kernel_launch(void* const* d_in, const int* in_sizes, int n_in,
                              void* d_out, int out_size) {
    const float* e     = (const float*)d_in[0];
    const float* f     = (const float*)d_in[1];
    const float* gamma = (const float*)d_in[2];
    const float* W     = (const float*)d_in[3];
    const float* bias  = (const float*)d_in[4];
    float* out = (float*)d_out;

    k_u<<<dim3(Dd / 128, Bb), 256>>>(e, W, gamma);
    k_s<<<dim3(Nn / 128, 2, Bb), 128>>>(f);
    k3_softmax<<<Bb * Tt, 256>>>();
    k_m<<<dim3(Dd / 128, 2, Bb), 128>>>(f);
    k_c<<<dim3(Kk / 64, Bb), 256>>>(W, bias);
    k5_norms<<<Bb, 256>>>(e);
    k6_cos<<<dim3(2, Bb), 256>>>(e, out);
}